// round 7
// baseline (speedup 1.0000x reference)
#include <cuda_runtime.h>
#include <cuda_fp16.h>
#include <cstdint>

#define BZ 32
#define CH 64
#define HH 128
#define WW 128
#define RROWS 4          // output rows per CTA
#define HW (HH * WW)
#define MPW 132          // words per c2-row of Mp (128 px + 4 pad): conflict-free
#define WP_STRIDE 33     // words per o-row of packed weights (aliased into ring slot 0)
#define ZSL 68           // words per o-row of a z ring slot (64 px-pairs + 4 pad)

// dynamic smem layout (bytes):
//   Mp    uint32_t[32*132]   @ 0      (16896)  fp16x2 x row, [c2][px]
//   ring  uint32_t[3][64*68] @ 16896  (3*17408=52224)  fp16x2 z rows
//         (Wp aliases ring slot 0 during phase 0 only)
//   BiasS float[64]          @ 69120  (256)
#define SMEM_BYTES 69376

static __device__ __forceinline__ float2 h2f(uint32_t w) {
    return __half22float2(*reinterpret_cast<__half2*>(&w));
}

__global__ __launch_bounds__(256, 3)
void denoise_fused(const float* __restrict__ x,
                   const float* __restrict__ conv_w,
                   const float* __restrict__ conv_b,
                   float* __restrict__ out) {
    extern __shared__ unsigned char smraw[];
    uint32_t* Mp    = reinterpret_cast<uint32_t*>(smraw);
    uint32_t* ring  = reinterpret_cast<uint32_t*>(smraw + 16896);
    uint32_t* Wp    = ring;                       // alias, consumed before ring use
    float*    BiasS = reinterpret_cast<float*>(smraw + 69120);

    const int tid  = threadIdx.x;
    const int warp = tid >> 5;
    const int lane = tid & 31;

    const int b  = blockIdx.y;
    const int h0 = blockIdx.x * RROWS;

    // ---------- phase 0: stage weights fp16x2 + bias ----------
    for (int i = tid; i < 64 * 32; i += 256) {
        const int o = i >> 5, c2 = i & 31;
        const float2 wv = reinterpret_cast<const float2*>(conv_w)[o * 32 + c2];
        __half2 pk = __floats2half2_rn(wv.x, wv.y);
        Wp[o * WP_STRIDE + c2] = *reinterpret_cast<uint32_t*>(&pk);
    }
    if (tid < 64) BiasS[tid] = conv_b[tid];
    __syncthreads();

    // a-fragments (weights) -> registers; after the next barrier Wp is dead.
    const int o0   = (warp >> 1) * 16;
    const int nsub = (warp & 1) * 64;
    const int lq = lane >> 2;   // 0..7
    const int lr = lane & 3;    // 0..3
    uint32_t a[4][4];
    #pragma unroll
    for (int kk = 0; kk < 4; kk++) {
        a[kk][0] = Wp[(o0 + lq)     * WP_STRIDE + kk * 8 + lr];
        a[kk][1] = Wp[(o0 + 8 + lq) * WP_STRIDE + kk * 8 + lr];
        a[kk][2] = Wp[(o0 + lq)     * WP_STRIDE + kk * 8 + 4 + lr];
        a[kk][3] = Wp[(o0 + 8 + lq) * WP_STRIDE + kk * 8 + 4 + lr];
    }
    const int oA = o0 + lq, oB = oA + 8;

    const float* xb = x   + (size_t)b * CH * HW;
    float*       ob = out + (size_t)b * CH * HW;

    // ---------- row pipeline: r = h0-1 .. h0+RROWS ----------
    #pragma unroll 1
    for (int r = h0 - 1; r <= h0 + RROWS; r++) {
        const int  slot  = (r + 3) % 3;
        uint32_t*  zs    = ring + slot * (64 * ZSL);
        const bool valid = (r >= 0) && (r < HH);

        // -- load x row r -> Mp (fp16x2 packed channel pairs) --
        if (valid) {
            #pragma unroll
            for (int it = 0; it < 4; it++) {
                const int g  = it * 256 + tid;      // 0..1023
                const int c2 = g >> 5;              // 0..31
                const int px = (g & 31) * 4;        // 0..124
                const float4 xa = *reinterpret_cast<const float4*>(
                    xb + (size_t)(2 * c2)     * HW + r * WW + px);
                const float4 xc = *reinterpret_cast<const float4*>(
                    xb + (size_t)(2 * c2 + 1) * HW + r * WW + px);
                __half2 p0 = __floats2half2_rn(xa.x, xc.x);
                __half2 p1 = __floats2half2_rn(xa.y, xc.y);
                __half2 p2 = __floats2half2_rn(xa.z, xc.z);
                __half2 p3 = __floats2half2_rn(xa.w, xc.w);
                uint4 pk = make_uint4(*reinterpret_cast<uint32_t*>(&p0),
                                      *reinterpret_cast<uint32_t*>(&p1),
                                      *reinterpret_cast<uint32_t*>(&p2),
                                      *reinterpret_cast<uint32_t*>(&p3));
                *reinterpret_cast<uint4*>(&Mp[c2 * MPW + px]) = pk;
            }
        }
        __syncthreads();   // Mp ready; prev iter's output phase done (slot reuse safe)

        // -- GEMM row r: z[o,p] = sum_c W[o,c]*x[c,p]  ->  ring slot (fp16x2) --
        if (valid) {
            #pragma unroll
            for (int nt = 0; nt < 8; nt++) {
                const int n0 = nsub + nt * 8;
                float acc0 = 0.f, acc1 = 0.f, acc2 = 0.f, acc3 = 0.f;
                #pragma unroll
                for (int kk = 0; kk < 4; kk++) {
                    const uint32_t b0 = Mp[(kk * 8 + lr)     * MPW + n0 + lq];
                    const uint32_t b1 = Mp[(kk * 8 + 4 + lr) * MPW + n0 + lq];
                    asm volatile(
                        "mma.sync.aligned.m16n8k16.row.col.f32.f16.f16.f32 "
                        "{%0,%1,%2,%3}, {%4,%5,%6,%7}, {%8,%9}, {%0,%1,%2,%3};\n"
                        : "+f"(acc0), "+f"(acc1), "+f"(acc2), "+f"(acc3)
                        : "r"(a[kk][0]), "r"(a[kk][1]), "r"(a[kk][2]), "r"(a[kk][3]),
                          "r"(b0), "r"(b1));
                }
                __half2 d01 = __floats2half2_rn(acc0, acc1);
                __half2 d23 = __floats2half2_rn(acc2, acc3);
                zs[oA * ZSL + (n0 >> 1) + lr] = *reinterpret_cast<uint32_t*>(&d01);
                zs[oB * ZSL + (n0 >> 1) + lr] = *reinterpret_cast<uint32_t*>(&d23);
            }
        } else {
            const uint4 z4 = make_uint4(0u, 0u, 0u, 0u);
            for (int i = tid; i < 1088; i += 256)   // 1088 uint4 = full slot
                *reinterpret_cast<uint4*>(&zs[i * 4]) = z4;
        }
        __syncthreads();   // z row r ready

        // -- output row ro = r-1 : 3x3 edge-clipped mean + residual + bias --
        const int ro = r - 1;
        if (ro >= h0 && ro < h0 + RROWS) {
            const uint32_t* zt = ring + ((ro - 1 + 3) % 3) * (64 * ZSL);
            const uint32_t* zm = ring + ((ro     + 3) % 3) * (64 * ZSL);
            const uint32_t* zb2 = ring + ((ro + 1 + 3) % 3) * (64 * ZSL);
            const float invh = (ro == 0 || ro == HH - 1) ? 0.5f : (1.0f / 3.0f);

            #pragma unroll
            for (int it = 0; it < 4; it++) {
                const int j  = it * 256 + tid;   // 0..1023
                const int o  = j >> 4;           // out channel
                const int q4 = j & 15;           // uint4 group (8 px)
                const int wb = o * ZSL + q4 * 4;

                // vertical 3-sum of 8 px (LDS.128 x3)
                const uint4 t4 = *reinterpret_cast<const uint4*>(&zt[wb]);
                const uint4 m4 = *reinterpret_cast<const uint4*>(&zm[wb]);
                const uint4 b4 = *reinterpret_cast<const uint4*>(&zb2[wb]);
                float v[8];
                {
                    float2 t, m, bt;
                    t = h2f(t4.x); m = h2f(m4.x); bt = h2f(b4.x);
                    v[0] = t.x + m.x + bt.x;  v[1] = t.y + m.y + bt.y;
                    t = h2f(t4.y); m = h2f(m4.y); bt = h2f(b4.y);
                    v[2] = t.x + m.x + bt.x;  v[3] = t.y + m.y + bt.y;
                    t = h2f(t4.z); m = h2f(m4.z); bt = h2f(b4.z);
                    v[4] = t.x + m.x + bt.x;  v[5] = t.y + m.y + bt.y;
                    t = h2f(t4.w); m = h2f(m4.w); bt = h2f(b4.w);
                    v[6] = t.x + m.x + bt.x;  v[7] = t.y + m.y + bt.y;
                }
                float vl = 0.f, vr = 0.f;
                if (q4 > 0) {
                    vl = h2f(zt[wb - 1]).y + h2f(zm[wb - 1]).y + h2f(zb2[wb - 1]).y;
                }
                if (q4 < 15) {
                    vr = h2f(zt[wb + 4]).x + h2f(zm[wb + 4]).x + h2f(zb2[wb + 4]).x;
                }

                // horizontal 3-sum + scale + residual + bias
                const int px0 = q4 * 8;
                const size_t off = (size_t)o * HW + ro * WW + px0;
                const float4 x0 = *reinterpret_cast<const float4*>(xb + off);
                const float4 x1 = *reinterpret_cast<const float4*>(xb + off + 4);
                const float bo = BiasS[o];
                const float iw  = (1.0f / 3.0f) * invh;
                const float iwL = (q4 == 0)  ? 0.5f * invh : iw;
                const float iwR = (q4 == 15) ? 0.5f * invh : iw;

                float4 o0v, o1v;
                o0v.x = x0.x + bo + (vl   + v[0] + v[1]) * iwL;
                o0v.y = x0.y + bo + (v[0] + v[1] + v[2]) * iw;
                o0v.z = x0.z + bo + (v[1] + v[2] + v[3]) * iw;
                o0v.w = x0.w + bo + (v[2] + v[3] + v[4]) * iw;
                o1v.x = x1.x + bo + (v[3] + v[4] + v[5]) * iw;
                o1v.y = x1.y + bo + (v[4] + v[5] + v[6]) * iw;
                o1v.z = x1.z + bo + (v[5] + v[6] + v[7]) * iw;
                o1v.w = x1.w + bo + (v[6] + v[7] + vr  ) * iwR;
                __stcs(reinterpret_cast<float4*>(ob + off), o0v);
                __stcs(reinterpret_cast<float4*>(ob + off + 4), o1v);
            }
        }
        // next iteration's first barrier fences slot reuse
    }
}

extern "C" void kernel_launch(void* const* d_in, const int* in_sizes, int n_in,
                              void* d_out, int out_size) {
    const float* x      = (const float*)d_in[0];
    const float* conv_w = (const float*)d_in[1];
    const float* conv_b = (const float*)d_in[2];
    float* out = (float*)d_out;

    cudaFuncSetAttribute(denoise_fused,
                         cudaFuncAttributeMaxDynamicSharedMemorySize, SMEM_BYTES);
    dim3 grid(HH / RROWS, BZ);               // 32 x 32 = 1024 CTAs
    denoise_fused<<<grid, 256, SMEM_BYTES>>>(x, conv_w, conv_b, out);
}

// round 8
// speedup vs baseline: 1.0716x; 1.0716x over previous
#include <cuda_runtime.h>
#include <cuda_fp16.h>
#include <cstdint>

#define BZ 32
#define CH 64
#define HH 128
#define WW 128
#define RROWS 4          // output rows per CTA
#define HW (HH * WW)
#define MPW 136          // words per c2-row of Mp (128 px + 8 pad): MPW%32==8 -> GEMM reads conflict-free
#define WP_STRIDE 33     // words per o-row of packed weights (aliased into ring slot 0)
#define ZSL 68           // words per o-row of a z ring slot (64 px-pairs + 4 pad)

// dynamic smem layout (bytes):
//   Mp    uint32_t[32*136]   @ 0      (17408)  fp16x2 x row, [c2][px]
//   ring  uint32_t[3][64*68] @ 17408  (3*17408=52224)  fp16x2 z rows
//         (Wp aliases ring slot 0 during phase 0 only)
//   BiasS float[64]          @ 69632  (256)
#define SMEM_BYTES 69888

static __device__ __forceinline__ float2 h2f(uint32_t w) {
    return __half22float2(*reinterpret_cast<__half2*>(&w));
}

__global__ __launch_bounds__(256, 3)
void denoise_fused(const float* __restrict__ x,
                   const float* __restrict__ conv_w,
                   const float* __restrict__ conv_b,
                   float* __restrict__ out) {
    extern __shared__ unsigned char smraw[];
    uint32_t* Mp    = reinterpret_cast<uint32_t*>(smraw);
    uint32_t* ring  = reinterpret_cast<uint32_t*>(smraw + 17408);
    uint32_t* Wp    = ring;                       // alias, consumed before ring use
    float*    BiasS = reinterpret_cast<float*>(smraw + 69632);

    const int tid  = threadIdx.x;
    const int warp = tid >> 5;
    const int lane = tid & 31;

    const int b  = blockIdx.y;
    const int h0 = blockIdx.x * RROWS;

    // ---------- phase 0: stage weights fp16x2 + bias ----------
    for (int i = tid; i < 64 * 32; i += 256) {
        const int o = i >> 5, c2 = i & 31;
        const float2 wv = reinterpret_cast<const float2*>(conv_w)[o * 32 + c2];
        __half2 pk = __floats2half2_rn(wv.x, wv.y);
        Wp[o * WP_STRIDE + c2] = *reinterpret_cast<uint32_t*>(&pk);
    }
    if (tid < 64) BiasS[tid] = conv_b[tid];
    __syncthreads();

    // a-fragments (weights) -> registers; after the next barrier Wp is dead.
    const int o0   = (warp >> 1) * 16;
    const int nsub = (warp & 1) * 64;
    const int lq = lane >> 2;   // 0..7
    const int lr = lane & 3;    // 0..3
    uint32_t a[4][4];
    #pragma unroll
    for (int kk = 0; kk < 4; kk++) {
        a[kk][0] = Wp[(o0 + lq)     * WP_STRIDE + kk * 8 + lr];
        a[kk][1] = Wp[(o0 + 8 + lq) * WP_STRIDE + kk * 8 + lr];
        a[kk][2] = Wp[(o0 + lq)     * WP_STRIDE + kk * 8 + 4 + lr];
        a[kk][3] = Wp[(o0 + 8 + lq) * WP_STRIDE + kk * 8 + 4 + lr];
    }
    const int oA = o0 + lq, oB = oA + 8;

    const float* xb = x   + (size_t)b * CH * HW;
    float*       ob = out + (size_t)b * CH * HW;

    // ---------- row pipeline: r = h0-1 .. h0+RROWS ----------
    #pragma unroll 1
    for (int r = h0 - 1; r <= h0 + RROWS; r++) {
        const int  slot  = (r + 3) % 3;
        uint32_t*  zs    = ring + slot * (64 * ZSL);
        const bool valid = (r >= 0) && (r < HH);

        // -- load x row r -> Mp (fp16x2 packed channel pairs) --
        if (valid) {
            #pragma unroll
            for (int it = 0; it < 4; it++) {
                const int g  = it * 256 + tid;      // 0..1023
                const int c2 = g >> 5;              // 0..31
                const int px = (g & 31) * 4;        // 0..124
                const float4 xa = *reinterpret_cast<const float4*>(
                    xb + (size_t)(2 * c2)     * HW + r * WW + px);
                const float4 xc = *reinterpret_cast<const float4*>(
                    xb + (size_t)(2 * c2 + 1) * HW + r * WW + px);
                __half2 p0 = __floats2half2_rn(xa.x, xc.x);
                __half2 p1 = __floats2half2_rn(xa.y, xc.y);
                __half2 p2 = __floats2half2_rn(xa.z, xc.z);
                __half2 p3 = __floats2half2_rn(xa.w, xc.w);
                uint4 pk = make_uint4(*reinterpret_cast<uint32_t*>(&p0),
                                      *reinterpret_cast<uint32_t*>(&p1),
                                      *reinterpret_cast<uint32_t*>(&p2),
                                      *reinterpret_cast<uint32_t*>(&p3));
                *reinterpret_cast<uint4*>(&Mp[c2 * MPW + px]) = pk;
            }
        }
        __syncthreads();   // Mp ready; prev iter's output phase done (slot reuse safe)

        // -- GEMM row r: z[o,p] = sum_c W[o,c]*x[c,p]  ->  ring slot (fp16x2) --
        if (valid) {
            #pragma unroll
            for (int nt = 0; nt < 8; nt++) {
                const int n0 = nsub + nt * 8;
                float acc0 = 0.f, acc1 = 0.f, acc2 = 0.f, acc3 = 0.f;
                #pragma unroll
                for (int kk = 0; kk < 4; kk++) {
                    const uint32_t b0 = Mp[(kk * 8 + lr)     * MPW + n0 + lq];
                    const uint32_t b1 = Mp[(kk * 8 + 4 + lr) * MPW + n0 + lq];
                    asm volatile(
                        "mma.sync.aligned.m16n8k16.row.col.f32.f16.f16.f32 "
                        "{%0,%1,%2,%3}, {%4,%5,%6,%7}, {%8,%9}, {%0,%1,%2,%3};\n"
                        : "+f"(acc0), "+f"(acc1), "+f"(acc2), "+f"(acc3)
                        : "r"(a[kk][0]), "r"(a[kk][1]), "r"(a[kk][2]), "r"(a[kk][3]),
                          "r"(b0), "r"(b1));
                }
                __half2 d01 = __floats2half2_rn(acc0, acc1);
                __half2 d23 = __floats2half2_rn(acc2, acc3);
                zs[oA * ZSL + (n0 >> 1) + lr] = *reinterpret_cast<uint32_t*>(&d01);
                zs[oB * ZSL + (n0 >> 1) + lr] = *reinterpret_cast<uint32_t*>(&d23);
            }
        } else {
            const uint4 z4 = make_uint4(0u, 0u, 0u, 0u);
            for (int i = tid; i < 1088; i += 256)   // 1088 uint4 = full slot
                *reinterpret_cast<uint4*>(&zs[i * 4]) = z4;
        }
        __syncthreads();   // z row r ready

        // -- output row ro = r-1 : 3x3 edge-clipped mean + residual + bias --
        const int ro = r - 1;
        if (ro >= h0 && ro < h0 + RROWS) {
            const uint32_t* zt  = ring + ((ro - 1 + 3) % 3) * (64 * ZSL);
            const uint32_t* zm  = ring + ((ro     + 3) % 3) * (64 * ZSL);
            const uint32_t* zb2 = ring + ((ro + 1 + 3) % 3) * (64 * ZSL);
            const float invh = (ro == 0 || ro == HH - 1) ? 0.5f : (1.0f / 3.0f);

            #pragma unroll
            for (int it = 0; it < 4; it++) {
                const int j  = it * 256 + tid;   // 0..1023
                const int o  = j >> 4;           // out channel
                const int q4 = j & 15;           // uint4 group (8 px); q4 == lane%16
                const int wb = o * ZSL + q4 * 4;

                // vertical 3-sum of 8 px (LDS.128 x3)
                const uint4 t4 = *reinterpret_cast<const uint4*>(&zt[wb]);
                const uint4 m4 = *reinterpret_cast<const uint4*>(&zm[wb]);
                const uint4 b4 = *reinterpret_cast<const uint4*>(&zb2[wb]);
                float v[8];
                {
                    float2 t, m, bt;
                    t = h2f(t4.x); m = h2f(m4.x); bt = h2f(b4.x);
                    v[0] = t.x + m.x + bt.x;  v[1] = t.y + m.y + bt.y;
                    t = h2f(t4.y); m = h2f(m4.y); bt = h2f(b4.y);
                    v[2] = t.x + m.x + bt.x;  v[3] = t.y + m.y + bt.y;
                    t = h2f(t4.z); m = h2f(m4.z); bt = h2f(b4.z);
                    v[4] = t.x + m.x + bt.x;  v[5] = t.y + m.y + bt.y;
                    t = h2f(t4.w); m = h2f(m4.w); bt = h2f(b4.w);
                    v[6] = t.x + m.x + bt.x;  v[7] = t.y + m.y + bt.y;
                }
                // left/right boundary vertical sums come from neighbor lanes:
                // lane-1 holds v[7] of the previous 8-px group (same channel),
                // lane+1 holds v[0] of the next. Group edges q4==0 / q4==15 are
                // the image edges w=0 / w=127 -> clipped (0 contribution).
                const float vls = __shfl_sync(0xffffffffu, v[7], (lane - 1) & 31);
                const float vrs = __shfl_sync(0xffffffffu, v[0], (lane + 1) & 31);
                const float vl = (q4 == 0)  ? 0.f : vls;
                const float vr = (q4 == 15) ? 0.f : vrs;

                // horizontal 3-sum + scale + residual + bias
                const int px0 = q4 * 8;
                const size_t off = (size_t)o * HW + ro * WW + px0;
                const float4 x0 = *reinterpret_cast<const float4*>(xb + off);
                const float4 x1 = *reinterpret_cast<const float4*>(xb + off + 4);
                const float bo = BiasS[o];
                const float iw  = (1.0f / 3.0f) * invh;
                const float iwL = (q4 == 0)  ? 0.5f * invh : iw;
                const float iwR = (q4 == 15) ? 0.5f * invh : iw;

                float4 o0v, o1v;
                o0v.x = x0.x + bo + (vl   + v[0] + v[1]) * iwL;
                o0v.y = x0.y + bo + (v[0] + v[1] + v[2]) * iw;
                o0v.z = x0.z + bo + (v[1] + v[2] + v[3]) * iw;
                o0v.w = x0.w + bo + (v[2] + v[3] + v[4]) * iw;
                o1v.x = x1.x + bo + (v[3] + v[4] + v[5]) * iw;
                o1v.y = x1.y + bo + (v[4] + v[5] + v[6]) * iw;
                o1v.z = x1.z + bo + (v[5] + v[6] + v[7]) * iw;
                o1v.w = x1.w + bo + (v[6] + v[7] + vr  ) * iwR;
                __stcs(reinterpret_cast<float4*>(ob + off), o0v);
                __stcs(reinterpret_cast<float4*>(ob + off + 4), o1v);
            }
        }
        // next iteration's first barrier fences slot reuse
    }
}

extern "C" void kernel_launch(void* const* d_in, const int* in_sizes, int n_in,
                              void* d_out, int out_size) {
    const float* x      = (const float*)d_in[0];
    const float* conv_w = (const float*)d_in[1];
    const float* conv_b = (const float*)d_in[2];
    float* out = (float*)d_out;

    cudaFuncSetAttribute(denoise_fused,
                         cudaFuncAttributeMaxDynamicSharedMemorySize, SMEM_BYTES);
    dim3 grid(HH / RROWS, BZ);               // 32 x 32 = 1024 CTAs
    denoise_fused<<<grid, 256, SMEM_BYTES>>>(x, conv_w, conv_b, out);
}

// round 9
// speedup vs baseline: 1.1953x; 1.1154x over previous
#include <cuda_runtime.h>
#include <cuda_fp16.h>
#include <cstdint>

#define BZ 32
#define CH 64
#define HH 128
#define WW 128
#define RROWS 4          // output rows per CTA
#define HW (HH * WW)
#define MPW 136          // words per c2-row of Mp (128 px + 8 pad): MPW%32==8 -> GEMM reads conflict-free
#define MPSLOT (32 * MPW)
#define WP_STRIDE 33     // words per o-row of packed weights (aliased into ring slot 0)
#define ZSL 68           // words per o-row of a z ring slot (64 px-pairs + 4 pad)

// dynamic smem layout (bytes):
//   Mp    uint32_t[2][32*136] @ 0      (34816)  fp16x2 x rows, double-buffered
//   ring  uint32_t[3][64*68]  @ 34816  (52224)  fp16x2 z rows
//         (Wp aliases ring slot 0 during phase 0 only)
//   BiasS float[64]           @ 87040  (256)
#define SMEM_BYTES 87296

static __device__ __forceinline__ float2 h2f(uint32_t w) {
    return __half22float2(*reinterpret_cast<__half2*>(&w));
}

__global__ __launch_bounds__(256, 2)
void denoise_fused(const float* __restrict__ x,
                   const float* __restrict__ conv_w,
                   const float* __restrict__ conv_b,
                   float* __restrict__ out) {
    extern __shared__ unsigned char smraw[];
    uint32_t* Mp    = reinterpret_cast<uint32_t*>(smraw);
    uint32_t* ring  = reinterpret_cast<uint32_t*>(smraw + 34816);
    uint32_t* Wp    = ring;                       // alias, consumed before ring use
    float*    BiasS = reinterpret_cast<float*>(smraw + 87040);

    const int tid  = threadIdx.x;
    const int warp = tid >> 5;
    const int lane = tid & 31;

    const int b  = blockIdx.y;
    const int h0 = blockIdx.x * RROWS;

    // ---------- phase 0: stage weights fp16x2 + bias ----------
    for (int i = tid; i < 64 * 32; i += 256) {
        const int o = i >> 5, c2 = i & 31;
        const float2 wv = reinterpret_cast<const float2*>(conv_w)[o * 32 + c2];
        __half2 pk = __floats2half2_rn(wv.x, wv.y);
        Wp[o * WP_STRIDE + c2] = *reinterpret_cast<uint32_t*>(&pk);
    }
    if (tid < 64) BiasS[tid] = conv_b[tid];
    __syncthreads();

    // a-fragments (weights) -> registers; after the next barrier Wp is dead.
    const int o0   = (warp >> 1) * 16;
    const int nsub = (warp & 1) * 64;
    const int lq = lane >> 2;   // 0..7
    const int lr = lane & 3;    // 0..3
    uint32_t a[4][4];
    #pragma unroll
    for (int kk = 0; kk < 4; kk++) {
        a[kk][0] = Wp[(o0 + lq)     * WP_STRIDE + kk * 8 + lr];
        a[kk][1] = Wp[(o0 + 8 + lq) * WP_STRIDE + kk * 8 + lr];
        a[kk][2] = Wp[(o0 + lq)     * WP_STRIDE + kk * 8 + 4 + lr];
        a[kk][3] = Wp[(o0 + 8 + lq) * WP_STRIDE + kk * 8 + 4 + lr];
    }
    const int oA = o0 + lq, oB = oA + 8;

    const float* xb = x   + (size_t)b * CH * HW;
    float*       ob = out + (size_t)b * CH * HW;

    // per-thread load coordinates (c2 = it*8 + warp, px = lane*4)
    const int pxl = lane * 4;

    // ---------- prologue: prefetch row h0-1 into registers ----------
    float4 pxa[4], pxc[4];
    if (h0 - 1 >= 0) {
        #pragma unroll
        for (int it = 0; it < 4; it++) {
            const int c2 = it * 8 + warp;
            pxa[it] = *reinterpret_cast<const float4*>(
                xb + (size_t)(2 * c2)     * HW + (h0 - 1) * WW + pxl);
            pxc[it] = *reinterpret_cast<const float4*>(
                xb + (size_t)(2 * c2 + 1) * HW + (h0 - 1) * WW + pxl);
        }
    }

    // ---------- row pipeline: r = h0-1 .. h0+RROWS ----------
    #pragma unroll 1
    for (int r = h0 - 1; r <= h0 + RROWS; r++) {
        const int  slot  = (r + 3) % 3;
        uint32_t*  zs    = ring + slot * (64 * ZSL);
        const bool valid = (r >= 0) && (r < HH);
        uint32_t*  mp    = Mp + (r & 1) * MPSLOT;

        // -- commit prefetched row r -> Mp[r&1] (fp16x2 packed channel pairs) --
        if (valid) {
            #pragma unroll
            for (int it = 0; it < 4; it++) {
                const int c2 = it * 8 + warp;
                __half2 p0 = __floats2half2_rn(pxa[it].x, pxc[it].x);
                __half2 p1 = __floats2half2_rn(pxa[it].y, pxc[it].y);
                __half2 p2 = __floats2half2_rn(pxa[it].z, pxc[it].z);
                __half2 p3 = __floats2half2_rn(pxa[it].w, pxc[it].w);
                uint4 pk = make_uint4(*reinterpret_cast<uint32_t*>(&p0),
                                      *reinterpret_cast<uint32_t*>(&p1),
                                      *reinterpret_cast<uint32_t*>(&p2),
                                      *reinterpret_cast<uint32_t*>(&p3));
                *reinterpret_cast<uint4*>(&mp[c2 * MPW + pxl]) = pk;
            }
        }

        // -- issue prefetch for row r+1 (latency hidden behind GEMM+epilogue) --
        const int rn = r + 1;
        if (rn <= h0 + RROWS && rn < HH) {
            #pragma unroll
            for (int it = 0; it < 4; it++) {
                const int c2 = it * 8 + warp;
                pxa[it] = *reinterpret_cast<const float4*>(
                    xb + (size_t)(2 * c2)     * HW + rn * WW + pxl);
                pxc[it] = *reinterpret_cast<const float4*>(
                    xb + (size_t)(2 * c2 + 1) * HW + rn * WW + pxl);
            }
        }
        __syncthreads();   // Mp[r&1] ready; ring slot (r-2) free for reuse

        // -- GEMM row r: z[o,p] = sum_c W[o,c]*x[c,p]  ->  ring slot (fp16x2) --
        if (valid) {
            #pragma unroll
            for (int nt = 0; nt < 8; nt++) {
                const int n0 = nsub + nt * 8;
                float acc0 = 0.f, acc1 = 0.f, acc2 = 0.f, acc3 = 0.f;
                #pragma unroll
                for (int kk = 0; kk < 4; kk++) {
                    const uint32_t b0 = mp[(kk * 8 + lr)     * MPW + n0 + lq];
                    const uint32_t b1 = mp[(kk * 8 + 4 + lr) * MPW + n0 + lq];
                    asm volatile(
                        "mma.sync.aligned.m16n8k16.row.col.f32.f16.f16.f32 "
                        "{%0,%1,%2,%3}, {%4,%5,%6,%7}, {%8,%9}, {%0,%1,%2,%3};\n"
                        : "+f"(acc0), "+f"(acc1), "+f"(acc2), "+f"(acc3)
                        : "r"(a[kk][0]), "r"(a[kk][1]), "r"(a[kk][2]), "r"(a[kk][3]),
                          "r"(b0), "r"(b1));
                }
                __half2 d01 = __floats2half2_rn(acc0, acc1);
                __half2 d23 = __floats2half2_rn(acc2, acc3);
                zs[oA * ZSL + (n0 >> 1) + lr] = *reinterpret_cast<uint32_t*>(&d01);
                zs[oB * ZSL + (n0 >> 1) + lr] = *reinterpret_cast<uint32_t*>(&d23);
            }
        } else {
            const uint4 z4 = make_uint4(0u, 0u, 0u, 0u);
            for (int i = tid; i < 1088; i += 256)   // 1088 uint4 = full slot
                *reinterpret_cast<uint4*>(&zs[i * 4]) = z4;
        }
        __syncthreads();   // z row r ready

        // -- output row ro = r-1 : 3x3 edge-clipped mean + residual + bias --
        const int ro = r - 1;
        if (ro >= h0 && ro < h0 + RROWS) {
            const uint32_t* zt  = ring + ((ro - 1 + 3) % 3) * (64 * ZSL);
            const uint32_t* zm  = ring + ((ro     + 3) % 3) * (64 * ZSL);
            const uint32_t* zb2 = ring + ((ro + 1 + 3) % 3) * (64 * ZSL);
            const float invh = (ro == 0 || ro == HH - 1) ? 0.5f : (1.0f / 3.0f);

            #pragma unroll
            for (int it = 0; it < 4; it++) {
                const int j  = it * 256 + tid;   // 0..1023
                const int o  = j >> 4;           // out channel
                const int q4 = j & 15;           // uint4 group (8 px); q4 == lane%16
                const int wb = o * ZSL + q4 * 4;

                // vertical 3-sum of 8 px (LDS.128 x3)
                const uint4 t4 = *reinterpret_cast<const uint4*>(&zt[wb]);
                const uint4 m4 = *reinterpret_cast<const uint4*>(&zm[wb]);
                const uint4 b4 = *reinterpret_cast<const uint4*>(&zb2[wb]);
                float v[8];
                {
                    float2 t, m, bt;
                    t = h2f(t4.x); m = h2f(m4.x); bt = h2f(b4.x);
                    v[0] = t.x + m.x + bt.x;  v[1] = t.y + m.y + bt.y;
                    t = h2f(t4.y); m = h2f(m4.y); bt = h2f(b4.y);
                    v[2] = t.x + m.x + bt.x;  v[3] = t.y + m.y + bt.y;
                    t = h2f(t4.z); m = h2f(m4.z); bt = h2f(b4.z);
                    v[4] = t.x + m.x + bt.x;  v[5] = t.y + m.y + bt.y;
                    t = h2f(t4.w); m = h2f(m4.w); bt = h2f(b4.w);
                    v[6] = t.x + m.x + bt.x;  v[7] = t.y + m.y + bt.y;
                }
                // left/right boundary vertical sums via neighbor lanes
                const float vls = __shfl_sync(0xffffffffu, v[7], (lane - 1) & 31);
                const float vrs = __shfl_sync(0xffffffffu, v[0], (lane + 1) & 31);
                const float vl = (q4 == 0)  ? 0.f : vls;
                const float vr = (q4 == 15) ? 0.f : vrs;

                // horizontal 3-sum + scale + residual + bias
                const int px0 = q4 * 8;
                const size_t off = (size_t)o * HW + ro * WW + px0;
                const float4 x0 = *reinterpret_cast<const float4*>(xb + off);
                const float4 x1 = *reinterpret_cast<const float4*>(xb + off + 4);
                const float bo = BiasS[o];
                const float iw  = (1.0f / 3.0f) * invh;
                const float iwL = (q4 == 0)  ? 0.5f * invh : iw;
                const float iwR = (q4 == 15) ? 0.5f * invh : iw;

                float4 o0v, o1v;
                o0v.x = x0.x + bo + (vl   + v[0] + v[1]) * iwL;
                o0v.y = x0.y + bo + (v[0] + v[1] + v[2]) * iw;
                o0v.z = x0.z + bo + (v[1] + v[2] + v[3]) * iw;
                o0v.w = x0.w + bo + (v[2] + v[3] + v[4]) * iw;
                o1v.x = x1.x + bo + (v[3] + v[4] + v[5]) * iw;
                o1v.y = x1.y + bo + (v[4] + v[5] + v[6]) * iw;
                o1v.z = x1.z + bo + (v[5] + v[6] + v[7]) * iw;
                o1v.w = x1.w + bo + (v[6] + v[7] + vr  ) * iwR;
                __stcs(reinterpret_cast<float4*>(ob + off), o0v);
                __stcs(reinterpret_cast<float4*>(ob + off + 4), o1v);
            }
        }
        // next iteration's first barrier fences ring-slot reuse
    }
}

extern "C" void kernel_launch(void* const* d_in, const int* in_sizes, int n_in,
                              void* d_out, int out_size) {
    const float* x      = (const float*)d_in[0];
    const float* conv_w = (const float*)d_in[1];
    const float* conv_b = (const float*)d_in[2];
    float* out = (float*)d_out;

    cudaFuncSetAttribute(denoise_fused,
                         cudaFuncAttributeMaxDynamicSharedMemorySize, SMEM_BYTES);
    dim3 grid(HH / RROWS, BZ);               // 32 x 32 = 1024 CTAs
    denoise_fused<<<grid, 256, SMEM_BYTES>>>(x, conv_w, conv_b, out);
}

// round 10
// speedup vs baseline: 1.2625x; 1.0563x over previous
#include <cuda_runtime.h>
#include <cuda_fp16.h>
#include <cstdint>

#define BZ 32
#define CH 64
#define HH 128
#define WW 128
#define RROWS 8          // output rows per CTA (processed 2 per iteration)
#define HW (HH * WW)
#define MPW 136          // words per c2-row of Mp: MPW%32==8 -> GEMM reads conflict-free
#define MPSLOT (32 * MPW)        // 4352 words per row-slot
#define WP_STRIDE 33     // words per o-row of packed weights (aliased into ring)
#define ZSL 68           // words per o-row of a z ring slot (64 px-pairs + 4 pad)
#define RINGSLOT (64 * ZSL)      // 4352 words per z row-slot

// dynamic smem layout (bytes):
//   Mp    uint32_t[4][32*136] @ 0       (69632)  fp16x2 x rows, 2 pair-buffers x 2 rows
//   ring  uint32_t[4][64*68]  @ 69632   (69632)  fp16x2 z rows, 4-slot ring
//         (Wp aliases ring start during phase 0 only)
//   BiasS float[64]           @ 139264  (256)
#define SMEM_BYTES 139520

static __device__ __forceinline__ float2 h2f(uint32_t w) {
    return __half22float2(*reinterpret_cast<__half2*>(&w));
}

__global__ __launch_bounds__(512, 1)
void denoise_fused(const float* __restrict__ x,
                   const float* __restrict__ conv_w,
                   const float* __restrict__ conv_b,
                   float* __restrict__ out) {
    extern __shared__ unsigned char smraw[];
    uint32_t* Mp    = reinterpret_cast<uint32_t*>(smraw);
    uint32_t* ring  = reinterpret_cast<uint32_t*>(smraw + 69632);
    uint32_t* Wp    = ring;                       // alias, consumed before ring use
    float*    BiasS = reinterpret_cast<float*>(smraw + 139264);

    const int tid  = threadIdx.x;
    const int warp = tid >> 5;
    const int lane = tid & 31;

    const int b  = blockIdx.y;
    const int h0 = blockIdx.x * RROWS;

    // ---------- phase 0: stage weights fp16x2 + bias ----------
    for (int i = tid; i < 64 * 32; i += 512) {
        const int o = i >> 5, c2 = i & 31;
        const float2 wv = reinterpret_cast<const float2*>(conv_w)[o * 32 + c2];
        __half2 pk = __floats2half2_rn(wv.x, wv.y);
        Wp[o * WP_STRIDE + c2] = *reinterpret_cast<uint32_t*>(&pk);
    }
    if (tid < 64) BiasS[tid] = conv_b[tid];
    __syncthreads();

    // a-fragments (weights) -> registers; Wp dead after first loop barrier.
    const int wr   = warp & 7;          // within-row warp id (warps 8-15 = row 1)
    const int o0   = (wr >> 1) * 16;
    const int nsub = (wr & 1) * 64;
    const int lq = lane >> 2;   // 0..7
    const int lr = lane & 3;    // 0..3
    uint32_t a[4][4];
    #pragma unroll
    for (int kk = 0; kk < 4; kk++) {
        a[kk][0] = Wp[(o0 + lq)     * WP_STRIDE + kk * 8 + lr];
        a[kk][1] = Wp[(o0 + 8 + lq) * WP_STRIDE + kk * 8 + lr];
        a[kk][2] = Wp[(o0 + lq)     * WP_STRIDE + kk * 8 + 4 + lr];
        a[kk][3] = Wp[(o0 + 8 + lq) * WP_STRIDE + kk * 8 + 4 + lr];
    }
    const int oA = o0 + lq, oB = oA + 8;

    const float* xb = x   + (size_t)b * CH * HW;
    float*       ob = out + (size_t)b * CH * HW;

    // per-thread load coords: channel pair c2p, two 4-px groups (pxp, pxp+64)
    const int c2p = tid >> 4;           // 0..31
    const int pxp = (tid & 15) * 4;     // 0..60

    // ---------- prologue: prefetch rows h0-1, h0 into registers ----------
    float4 pa[2][2], pc[2][2];
    #pragma unroll
    for (int k = 0; k < 2; k++) {
        const int rr = h0 - 1 + k;
        if (rr >= 0) {
            #pragma unroll
            for (int g = 0; g < 2; g++) {
                pa[k][g] = *reinterpret_cast<const float4*>(
                    xb + (size_t)(2 * c2p)     * HW + rr * WW + pxp + 64 * g);
                pc[k][g] = *reinterpret_cast<const float4*>(
                    xb + (size_t)(2 * c2p + 1) * HW + rr * WW + pxp + 64 * g);
            }
        }
    }

    // ---------- pipeline: 5 iterations, 2 GEMM rows + 2 output rows each ----------
    #pragma unroll 1
    for (int i = 0; i < 5; i++) {
        const int r0 = h0 - 1 + 2 * i;            // GEMM rows r0, r0+1
        uint32_t* mpb = Mp + (i & 1) * (2 * MPSLOT);

        // -- commit prefetched rows r0, r0+1 -> Mp pair buffer --
        #pragma unroll
        for (int k = 0; k < 2; k++) {
            const int rr = r0 + k;
            if (rr >= 0 && rr < HH) {
                uint32_t* mp = mpb + k * MPSLOT;
                #pragma unroll
                for (int g = 0; g < 2; g++) {
                    __half2 p0 = __floats2half2_rn(pa[k][g].x, pc[k][g].x);
                    __half2 p1 = __floats2half2_rn(pa[k][g].y, pc[k][g].y);
                    __half2 p2 = __floats2half2_rn(pa[k][g].z, pc[k][g].z);
                    __half2 p3 = __floats2half2_rn(pa[k][g].w, pc[k][g].w);
                    uint4 pk4 = make_uint4(*reinterpret_cast<uint32_t*>(&p0),
                                           *reinterpret_cast<uint32_t*>(&p1),
                                           *reinterpret_cast<uint32_t*>(&p2),
                                           *reinterpret_cast<uint32_t*>(&p3));
                    *reinterpret_cast<uint4*>(&mp[c2p * MPW + pxp + 64 * g]) = pk4;
                }
            }
        }

        // -- issue prefetch for rows r0+2, r0+3 (hidden behind GEMM+epilogue) --
        if (i < 4) {
            #pragma unroll
            for (int k = 0; k < 2; k++) {
                const int rr = r0 + 2 + k;        // >= 1 always
                if (rr < HH) {
                    #pragma unroll
                    for (int g = 0; g < 2; g++) {
                        pa[k][g] = *reinterpret_cast<const float4*>(
                            xb + (size_t)(2 * c2p)     * HW + rr * WW + pxp + 64 * g);
                        pc[k][g] = *reinterpret_cast<const float4*>(
                            xb + (size_t)(2 * c2p + 1) * HW + rr * WW + pxp + 64 * g);
                    }
                }
            }
        }
        __syncthreads();   // Mp pair ready; ring slots needed by prev epilogue free

        // -- GEMM: warps 0-7 -> row r0, warps 8-15 -> row r0+1 --
        {
            const int k  = warp >> 3;
            const int rr = r0 + k;
            uint32_t* zs = ring + ((rr + 4) & 3) * RINGSLOT;
            const uint32_t* mp = mpb + k * MPSLOT;
            if (rr >= 0 && rr < HH) {
                #pragma unroll
                for (int nt = 0; nt < 8; nt++) {
                    const int n0 = nsub + nt * 8;
                    float acc0 = 0.f, acc1 = 0.f, acc2 = 0.f, acc3 = 0.f;
                    #pragma unroll
                    for (int kk = 0; kk < 4; kk++) {
                        const uint32_t b0 = mp[(kk * 8 + lr)     * MPW + n0 + lq];
                        const uint32_t b1 = mp[(kk * 8 + 4 + lr) * MPW + n0 + lq];
                        asm volatile(
                            "mma.sync.aligned.m16n8k16.row.col.f32.f16.f16.f32 "
                            "{%0,%1,%2,%3}, {%4,%5,%6,%7}, {%8,%9}, {%0,%1,%2,%3};\n"
                            : "+f"(acc0), "+f"(acc1), "+f"(acc2), "+f"(acc3)
                            : "r"(a[kk][0]), "r"(a[kk][1]), "r"(a[kk][2]), "r"(a[kk][3]),
                              "r"(b0), "r"(b1));
                    }
                    __half2 d01 = __floats2half2_rn(acc0, acc1);
                    __half2 d23 = __floats2half2_rn(acc2, acc3);
                    zs[oA * ZSL + (n0 >> 1) + lr] = *reinterpret_cast<uint32_t*>(&d01);
                    zs[oB * ZSL + (n0 >> 1) + lr] = *reinterpret_cast<uint32_t*>(&d23);
                }
            } else {
                const int tidr = tid & 255;
                const uint4 z4 = make_uint4(0u, 0u, 0u, 0u);
                for (int jj = tidr; jj < 1088; jj += 256)   // 1088 uint4 = full slot
                    *reinterpret_cast<uint4*>(&zs[jj * 4]) = z4;
            }
        }
        __syncthreads();   // z rows r0, r0+1 ready

        // -- epilogue: output rows h0-2+2i (+0,+1); skip warm-up iteration --
        if (i > 0) {
            #pragma unroll
            for (int it = 0; it < 4; it++) {
                const int idx  = it * 512 + tid;
                const int orow = idx >> 4;       // 0..127
                const int rowk = orow & 1;       // lanes 0-15: row 0, 16-31: row 1
                const int o    = orow >> 1;      // out channel 0..63
                const int q4   = tid & 15;       // uint4 group (8 px)
                const int ro   = h0 - 2 + 2 * i + rowk;

                const uint32_t* zt  = ring + ((ro - 1 + 4) & 3) * RINGSLOT;
                const uint32_t* zm  = ring + ((ro     + 4) & 3) * RINGSLOT;
                const uint32_t* zb2 = ring + ((ro + 1)     & 3) * RINGSLOT;
                const float invh = (ro == 0 || ro == HH - 1) ? 0.5f : (1.0f / 3.0f);
                const int wb = o * ZSL + q4 * 4;

                // vertical 3-sum of 8 px (LDS.128 x3)
                const uint4 t4 = *reinterpret_cast<const uint4*>(&zt[wb]);
                const uint4 m4 = *reinterpret_cast<const uint4*>(&zm[wb]);
                const uint4 b4 = *reinterpret_cast<const uint4*>(&zb2[wb]);
                float v[8];
                {
                    float2 t, m, bt;
                    t = h2f(t4.x); m = h2f(m4.x); bt = h2f(b4.x);
                    v[0] = t.x + m.x + bt.x;  v[1] = t.y + m.y + bt.y;
                    t = h2f(t4.y); m = h2f(m4.y); bt = h2f(b4.y);
                    v[2] = t.x + m.x + bt.x;  v[3] = t.y + m.y + bt.y;
                    t = h2f(t4.z); m = h2f(m4.z); bt = h2f(b4.z);
                    v[4] = t.x + m.x + bt.x;  v[5] = t.y + m.y + bt.y;
                    t = h2f(t4.w); m = h2f(m4.w); bt = h2f(b4.w);
                    v[6] = t.x + m.x + bt.x;  v[7] = t.y + m.y + bt.y;
                }
                // boundary vertical sums via neighbor lanes (cross-half values
                // at lane 15<->16 are discarded by the q4 edge guards)
                const float vls = __shfl_sync(0xffffffffu, v[7], (lane - 1) & 31);
                const float vrs = __shfl_sync(0xffffffffu, v[0], (lane + 1) & 31);
                const float vl = (q4 == 0)  ? 0.f : vls;
                const float vr = (q4 == 15) ? 0.f : vrs;

                // horizontal 3-sum + scale + residual + bias
                const int px0 = q4 * 8;
                const size_t off = (size_t)o * HW + ro * WW + px0;
                const float4 x0 = *reinterpret_cast<const float4*>(xb + off);
                const float4 x1 = *reinterpret_cast<const float4*>(xb + off + 4);
                const float bo = BiasS[o];
                const float iw  = (1.0f / 3.0f) * invh;
                const float iwL = (q4 == 0)  ? 0.5f * invh : iw;
                const float iwR = (q4 == 15) ? 0.5f * invh : iw;

                float4 o0v, o1v;
                o0v.x = x0.x + bo + (vl   + v[0] + v[1]) * iwL;
                o0v.y = x0.y + bo + (v[0] + v[1] + v[2]) * iw;
                o0v.z = x0.z + bo + (v[1] + v[2] + v[3]) * iw;
                o0v.w = x0.w + bo + (v[2] + v[3] + v[4]) * iw;
                o1v.x = x1.x + bo + (v[3] + v[4] + v[5]) * iw;
                o1v.y = x1.y + bo + (v[4] + v[5] + v[6]) * iw;
                o1v.z = x1.z + bo + (v[5] + v[6] + v[7]) * iw;
                o1v.w = x1.w + bo + (v[6] + v[7] + vr  ) * iwR;
                __stcs(reinterpret_cast<float4*>(ob + off), o0v);
                __stcs(reinterpret_cast<float4*>(ob + off + 4), o1v);
            }
        }
        // next iteration's first barrier fences ring/Mp reuse
    }
}

extern "C" void kernel_launch(void* const* d_in, const int* in_sizes, int n_in,
                              void* d_out, int out_size) {
    const float* x      = (const float*)d_in[0];
    const float* conv_w = (const float*)d_in[1];
    const float* conv_b = (const float*)d_in[2];
    float* out = (float*)d_out;

    cudaFuncSetAttribute(denoise_fused,
                         cudaFuncAttributeMaxDynamicSharedMemorySize, SMEM_BYTES);
    dim3 grid(HH / RROWS, BZ);               // 16 x 32 = 512 CTAs
    denoise_fused<<<grid, 512, SMEM_BYTES>>>(x, conv_w, conv_b, out);
}

// round 11
// speedup vs baseline: 1.2871x; 1.0195x over previous
#include <cuda_runtime.h>
#include <cuda_fp16.h>
#include <cstdint>

#define BZ 32
#define CH 64
#define HH 128
#define WW 128
#define RROWS 8          // output rows per CTA (processed 2 per iteration)
#define HW (HH * WW)
#define MPW 136          // words per c2-row of Mp: MPW%32==8 -> GEMM reads conflict-free
#define MPSLOT (32 * MPW)        // 4352 words per row-slot
#define WP_STRIDE 33     // words per o-row of packed weights (aliased into ring)
#define ZSL 68           // words per o-row of a z ring slot (64 px-pairs + 4 pad)
#define RINGSLOT (64 * ZSL)      // 4352 words per z row-slot

// dynamic smem layout (bytes):
//   Mp    uint32_t[4][32*136] @ 0       (69632)  fp16x2 x rows, 2 pair-buffers x 2 rows
//   ring  uint32_t[4][64*68]  @ 69632   (69632)  fp16x2 z rows, 4-slot ring
//         (Wp aliases ring start during phase 0 only)
//   BiasS float[64]           @ 139264  (256)
#define SMEM_BYTES 139520

static __device__ __forceinline__ float2 h2f(uint32_t w) {
    return __half22float2(*reinterpret_cast<__half2*>(&w));
}

__global__ __launch_bounds__(512, 1)
void denoise_fused(const float* __restrict__ x,
                   const float* __restrict__ conv_w,
                   const float* __restrict__ conv_b,
                   float* __restrict__ out) {
    extern __shared__ unsigned char smraw[];
    uint32_t* Mp    = reinterpret_cast<uint32_t*>(smraw);
    uint32_t* ring  = reinterpret_cast<uint32_t*>(smraw + 69632);
    uint32_t* Wp    = ring;                       // alias, consumed before ring use
    float*    BiasS = reinterpret_cast<float*>(smraw + 139264);

    const int tid  = threadIdx.x;
    const int warp = tid >> 5;
    const int lane = tid & 31;

    const int b  = blockIdx.y;
    const int h0 = blockIdx.x * RROWS;

    // ---------- phase 0: stage weights fp16x2 + bias ----------
    for (int i = tid; i < 64 * 32; i += 512) {
        const int o = i >> 5, c2 = i & 31;
        const float2 wv = reinterpret_cast<const float2*>(conv_w)[o * 32 + c2];
        __half2 pk = __floats2half2_rn(wv.x, wv.y);
        Wp[o * WP_STRIDE + c2] = *reinterpret_cast<uint32_t*>(&pk);
    }
    if (tid < 64) BiasS[tid] = conv_b[tid];
    __syncthreads();

    // GEMM warp tiling: 2 M-tiles x 4 N-slices per row (B fragments reused 2x).
    const int wr    = warp & 7;         // within-row warp id (warps 8-15 = row 1)
    const int mgrp  = wr & 1;           // 0..1 -> o0 = mgrp*32 (tiles o0, o0+16)
    const int nsl   = wr >> 1;          // 0..3 -> 32-px slice
    const int o0    = mgrp * 32;
    const int nsub  = nsl * 32;
    const int lq = lane >> 2;   // 0..7
    const int lr = lane & 3;    // 0..3

    // a-fragments: 2 M-tiles x 4 k-steps x 4 regs = 32 regs
    uint32_t a[2][4][4];
    #pragma unroll
    for (int mt = 0; mt < 2; mt++) {
        const int ot = o0 + mt * 16;
        #pragma unroll
        for (int kk = 0; kk < 4; kk++) {
            a[mt][kk][0] = Wp[(ot + lq)     * WP_STRIDE + kk * 8 + lr];
            a[mt][kk][1] = Wp[(ot + 8 + lq) * WP_STRIDE + kk * 8 + lr];
            a[mt][kk][2] = Wp[(ot + lq)     * WP_STRIDE + kk * 8 + 4 + lr];
            a[mt][kk][3] = Wp[(ot + 8 + lq) * WP_STRIDE + kk * 8 + 4 + lr];
        }
    }

    const float* xb = x   + (size_t)b * CH * HW;
    float*       ob = out + (size_t)b * CH * HW;

    // per-thread load coords: channel pair c2p, two 4-px groups (pxp, pxp+64)
    const int c2p = tid >> 4;           // 0..31
    const int pxp = (tid & 15) * 4;     // 0..60

    // ---------- prologue: prefetch rows h0-1, h0 into registers ----------
    float4 pa[2][2], pc[2][2];
    #pragma unroll
    for (int k = 0; k < 2; k++) {
        const int rr = h0 - 1 + k;
        if (rr >= 0) {
            #pragma unroll
            for (int g = 0; g < 2; g++) {
                pa[k][g] = *reinterpret_cast<const float4*>(
                    xb + (size_t)(2 * c2p)     * HW + rr * WW + pxp + 64 * g);
                pc[k][g] = *reinterpret_cast<const float4*>(
                    xb + (size_t)(2 * c2p + 1) * HW + rr * WW + pxp + 64 * g);
            }
        }
    }

    // ---------- pipeline: 5 iterations, 2 GEMM rows + 2 output rows each ----------
    #pragma unroll 1
    for (int i = 0; i < 5; i++) {
        const int r0 = h0 - 1 + 2 * i;            // GEMM rows r0, r0+1
        uint32_t* mpb = Mp + (i & 1) * (2 * MPSLOT);

        // -- commit prefetched rows r0, r0+1 -> Mp pair buffer --
        #pragma unroll
        for (int k = 0; k < 2; k++) {
            const int rr = r0 + k;
            if (rr >= 0 && rr < HH) {
                uint32_t* mp = mpb + k * MPSLOT;
                #pragma unroll
                for (int g = 0; g < 2; g++) {
                    __half2 p0 = __floats2half2_rn(pa[k][g].x, pc[k][g].x);
                    __half2 p1 = __floats2half2_rn(pa[k][g].y, pc[k][g].y);
                    __half2 p2 = __floats2half2_rn(pa[k][g].z, pc[k][g].z);
                    __half2 p3 = __floats2half2_rn(pa[k][g].w, pc[k][g].w);
                    uint4 pk4 = make_uint4(*reinterpret_cast<uint32_t*>(&p0),
                                           *reinterpret_cast<uint32_t*>(&p1),
                                           *reinterpret_cast<uint32_t*>(&p2),
                                           *reinterpret_cast<uint32_t*>(&p3));
                    *reinterpret_cast<uint4*>(&mp[c2p * MPW + pxp + 64 * g]) = pk4;
                }
            }
        }

        // -- issue prefetch for rows r0+2, r0+3 (hidden behind GEMM+epilogue) --
        if (i < 4) {
            #pragma unroll
            for (int k = 0; k < 2; k++) {
                const int rr = r0 + 2 + k;        // >= 1 always
                if (rr < HH) {
                    #pragma unroll
                    for (int g = 0; g < 2; g++) {
                        pa[k][g] = *reinterpret_cast<const float4*>(
                            xb + (size_t)(2 * c2p)     * HW + rr * WW + pxp + 64 * g);
                        pc[k][g] = *reinterpret_cast<const float4*>(
                            xb + (size_t)(2 * c2p + 1) * HW + rr * WW + pxp + 64 * g);
                    }
                }
            }
        }
        __syncthreads();   // Mp pair ready; ring slots needed by prev epilogue free

        // -- GEMM: warps 0-7 -> row r0, warps 8-15 -> row r0+1 --
        {
            const int k  = warp >> 3;
            const int rr = r0 + k;
            uint32_t* zs = ring + ((rr + 4) & 3) * RINGSLOT;
            const uint32_t* mp = mpb + k * MPSLOT;
            if (rr >= 0 && rr < HH) {
                #pragma unroll
                for (int nt = 0; nt < 4; nt++) {
                    const int n0 = nsub + nt * 8;
                    float ac[2][4];
                    #pragma unroll
                    for (int mt = 0; mt < 2; mt++)
                        ac[mt][0] = ac[mt][1] = ac[mt][2] = ac[mt][3] = 0.f;
                    #pragma unroll
                    for (int kk = 0; kk < 4; kk++) {
                        const uint32_t b0 = mp[(kk * 8 + lr)     * MPW + n0 + lq];
                        const uint32_t b1 = mp[(kk * 8 + 4 + lr) * MPW + n0 + lq];
                        #pragma unroll
                        for (int mt = 0; mt < 2; mt++) {
                            asm volatile(
                                "mma.sync.aligned.m16n8k16.row.col.f32.f16.f16.f32 "
                                "{%0,%1,%2,%3}, {%4,%5,%6,%7}, {%8,%9}, {%0,%1,%2,%3};\n"
                                : "+f"(ac[mt][0]), "+f"(ac[mt][1]),
                                  "+f"(ac[mt][2]), "+f"(ac[mt][3])
                                : "r"(a[mt][kk][0]), "r"(a[mt][kk][1]),
                                  "r"(a[mt][kk][2]), "r"(a[mt][kk][3]),
                                  "r"(b0), "r"(b1));
                        }
                    }
                    #pragma unroll
                    for (int mt = 0; mt < 2; mt++) {
                        const int oA = o0 + mt * 16 + lq;
                        __half2 d01 = __floats2half2_rn(ac[mt][0], ac[mt][1]);
                        __half2 d23 = __floats2half2_rn(ac[mt][2], ac[mt][3]);
                        zs[oA       * ZSL + (n0 >> 1) + lr] = *reinterpret_cast<uint32_t*>(&d01);
                        zs[(oA + 8) * ZSL + (n0 >> 1) + lr] = *reinterpret_cast<uint32_t*>(&d23);
                    }
                }
            } else {
                const int tidr = tid & 255;
                const uint4 z4 = make_uint4(0u, 0u, 0u, 0u);
                for (int jj = tidr; jj < 1088; jj += 256)   // 1088 uint4 = full slot
                    *reinterpret_cast<uint4*>(&zs[jj * 4]) = z4;
            }
        }
        __syncthreads();   // z rows r0, r0+1 ready

        // -- epilogue: output rows h0-2+2i (+0,+1); skip warm-up iteration --
        if (i > 0) {
            #pragma unroll
            for (int it = 0; it < 4; it++) {
                const int idx  = it * 512 + tid;
                const int orow = idx >> 4;       // 0..127
                const int rowk = orow & 1;       // lanes 0-15: row 0, 16-31: row 1
                const int o    = orow >> 1;      // out channel 0..63
                const int q4   = tid & 15;       // uint4 group (8 px)
                const int ro   = h0 - 2 + 2 * i + rowk;

                const uint32_t* zt  = ring + ((ro - 1 + 4) & 3) * RINGSLOT;
                const uint32_t* zm  = ring + ((ro     + 4) & 3) * RINGSLOT;
                const uint32_t* zb2 = ring + ((ro + 1)     & 3) * RINGSLOT;
                const float invh = (ro == 0 || ro == HH - 1) ? 0.5f : (1.0f / 3.0f);
                const int wb = o * ZSL + q4 * 4;

                // vertical 3-sum of 8 px (LDS.128 x3)
                const uint4 t4 = *reinterpret_cast<const uint4*>(&zt[wb]);
                const uint4 m4 = *reinterpret_cast<const uint4*>(&zm[wb]);
                const uint4 b4 = *reinterpret_cast<const uint4*>(&zb2[wb]);
                float v[8];
                {
                    float2 t, m, bt;
                    t = h2f(t4.x); m = h2f(m4.x); bt = h2f(b4.x);
                    v[0] = t.x + m.x + bt.x;  v[1] = t.y + m.y + bt.y;
                    t = h2f(t4.y); m = h2f(m4.y); bt = h2f(b4.y);
                    v[2] = t.x + m.x + bt.x;  v[3] = t.y + m.y + bt.y;
                    t = h2f(t4.z); m = h2f(m4.z); bt = h2f(b4.z);
                    v[4] = t.x + m.x + bt.x;  v[5] = t.y + m.y + bt.y;
                    t = h2f(t4.w); m = h2f(m4.w); bt = h2f(b4.w);
                    v[6] = t.x + m.x + bt.x;  v[7] = t.y + m.y + bt.y;
                }
                // boundary vertical sums via neighbor lanes (cross-half values
                // at lane 15<->16 are discarded by the q4 edge guards)
                const float vls = __shfl_sync(0xffffffffu, v[7], (lane - 1) & 31);
                const float vrs = __shfl_sync(0xffffffffu, v[0], (lane + 1) & 31);
                const float vl = (q4 == 0)  ? 0.f : vls;
                const float vr = (q4 == 15) ? 0.f : vrs;

                // horizontal 3-sum + scale + residual + bias
                const int px0 = q4 * 8;
                const size_t off = (size_t)o * HW + ro * WW + px0;
                const float4 x0 = *reinterpret_cast<const float4*>(xb + off);
                const float4 x1 = *reinterpret_cast<const float4*>(xb + off + 4);
                const float bo = BiasS[o];
                const float iw  = (1.0f / 3.0f) * invh;
                const float iwL = (q4 == 0)  ? 0.5f * invh : iw;
                const float iwR = (q4 == 15) ? 0.5f * invh : iw;

                float4 o0v, o1v;
                o0v.x = x0.x + bo + (vl   + v[0] + v[1]) * iwL;
                o0v.y = x0.y + bo + (v[0] + v[1] + v[2]) * iw;
                o0v.z = x0.z + bo + (v[1] + v[2] + v[3]) * iw;
                o0v.w = x0.w + bo + (v[2] + v[3] + v[4]) * iw;
                o1v.x = x1.x + bo + (v[3] + v[4] + v[5]) * iw;
                o1v.y = x1.y + bo + (v[4] + v[5] + v[6]) * iw;
                o1v.z = x1.z + bo + (v[5] + v[6] + v[7]) * iw;
                o1v.w = x1.w + bo + (v[6] + v[7] + vr  ) * iwR;
                __stcs(reinterpret_cast<float4*>(ob + off), o0v);
                __stcs(reinterpret_cast<float4*>(ob + off + 4), o1v);
            }
        }
        // next iteration's first barrier fences ring/Mp reuse
    }
}

extern "C" void kernel_launch(void* const* d_in, const int* in_sizes, int n_in,
                              void* d_out, int out_size) {
    const float* x      = (const float*)d_in[0];
    const float* conv_w = (const float*)d_in[1];
    const float* conv_b = (const float*)d_in[2];
    float* out = (float*)d_out;

    cudaFuncSetAttribute(denoise_fused,
                         cudaFuncAttributeMaxDynamicSharedMemorySize, SMEM_BYTES);
    dim3 grid(HH / RROWS, BZ);               // 16 x 32 = 512 CTAs
    denoise_fused<<<grid, 512, SMEM_BYTES>>>(x, conv_w, conv_b, out);
}